// round 1
// baseline (speedup 1.0000x reference)
#include <cuda_runtime.h>
#include <stdint.h>

#define USER_NUM 100000
#define ITEM_NUM 200000
#define NNODES   (USER_NUM + ITEM_NUM)   // 300000
#define EMB      64
#define TOT      (NNODES * EMB)          // 19,200,000 floats
#define TOT4     (TOT / 4)               // 4,800,000 float4

// Scratch ego buffers (no cudaMalloc allowed).
__device__ float g_bufA[TOT];
__device__ float g_bufB[TOT];

// ---------------------------------------------------------------------------
// init: A = concat(user, item); acc = A; B = 0      (fully fused, one pass)
// ---------------------------------------------------------------------------
__global__ void init_kernel(const float4* __restrict__ user,
                            const float4* __restrict__ item,
                            float4* __restrict__ acc,
                            float4* __restrict__ A,
                            float4* __restrict__ B) {
    int i = blockIdx.x * blockDim.x + threadIdx.x;
    if (i >= TOT4) return;
    const int ub = USER_NUM * EMB / 4;   // 1,600,000
    float4 v = (i < ub) ? __ldg(&user[i]) : __ldg(&item[i - ub]);
    A[i]   = v;
    acc[i] = v;
    B[i]   = make_float4(0.f, 0.f, 0.f, 0.f);
}

// ---------------------------------------------------------------------------
// SpMM (COO): y[rows[e]] += vals[e] * x[cols[e]]
// 16 lanes per edge, 4 floats per lane, vectorized no-return reduction.
// ---------------------------------------------------------------------------
__global__ void spmm_kernel(const float* __restrict__ vals,
                            const int*   __restrict__ rows,
                            const int*   __restrict__ cols,
                            const float4* __restrict__ x,
                            float* __restrict__ y,
                            int n_edges) {
    long long t = (long long)blockIdx.x * blockDim.x + threadIdx.x;
    int e = (int)(t >> 4);
    int l = (int)(t & 15);
    if (e >= n_edges) return;

    int   c = __ldg(cols + e);
    int   r = __ldg(rows + e);
    float v = __ldg(vals + e);

    float4 xv = __ldg(&x[(long long)c * 16 + l]);
    float4 p  = make_float4(xv.x * v, xv.y * v, xv.z * v, xv.w * v);

    float* dst = y + (long long)r * EMB + l * 4;
    asm volatile("red.global.add.v4.f32 [%0], {%1, %2, %3, %4};"
                 :: "l"(dst), "f"(p.x), "f"(p.y), "f"(p.z), "f"(p.w)
                 : "memory");
}

// ---------------------------------------------------------------------------
// finish: acc += next; zero the buffer the NEXT layer scatters into
// ---------------------------------------------------------------------------
__global__ void finish_kernel(float4* __restrict__ acc,
                              const float4* __restrict__ next,
                              float4* __restrict__ zbuf) {
    int i = blockIdx.x * blockDim.x + threadIdx.x;
    if (i >= TOT4) return;
    float4 a = acc[i];
    float4 n = next[i];
    a.x += n.x; a.y += n.y; a.z += n.z; a.w += n.w;
    acc[i]  = a;
    zbuf[i] = make_float4(0.f, 0.f, 0.f, 0.f);
}

// final layer: acc = (acc + next) * 0.25
__global__ void finish_last_kernel(float4* __restrict__ acc,
                                   const float4* __restrict__ next) {
    int i = blockIdx.x * blockDim.x + threadIdx.x;
    if (i >= TOT4) return;
    float4 a = acc[i];
    float4 n = next[i];
    a.x = (a.x + n.x) * 0.25f;
    a.y = (a.y + n.y) * 0.25f;
    a.z = (a.z + n.z) * 0.25f;
    a.w = (a.w + n.w) * 0.25f;
    acc[i] = a;
}

// ---------------------------------------------------------------------------
extern "C" void kernel_launch(void* const* d_in, const int* in_sizes, int n_in,
                              void* d_out, int out_size) {
    const float* user = (const float*)d_in[0];
    const float* item = (const float*)d_in[1];
    const float* vals = (const float*)d_in[2];
    const int*   rows = (const int*)  d_in[3];
    const int*   cols = (const int*)  d_in[4];
    const int n_edges = in_sizes[2];

    float* acc = (float*)d_out;

    float *A, *B;
    cudaGetSymbolAddress((void**)&A, g_bufA);
    cudaGetSymbolAddress((void**)&B, g_bufB);

    const int threads = 256;
    const int grid_ew = (TOT4 + threads - 1) / threads;                       // elementwise
    const long long sp_threads = (long long)n_edges * 16;
    const int grid_sp = (int)((sp_threads + threads - 1) / threads);          // spmm

    // init: A = ego0, acc = ego0, B = 0
    init_kernel<<<grid_ew, threads>>>((const float4*)user, (const float4*)item,
                                      (float4*)acc, (float4*)A, (float4*)B);

    // layer 1: B = Adj * A ; acc += B ; zero A
    spmm_kernel<<<grid_sp, threads>>>(vals, rows, cols, (const float4*)A, B, n_edges);
    finish_kernel<<<grid_ew, threads>>>((float4*)acc, (const float4*)B, (float4*)A);

    // layer 2: A = Adj * B ; acc += A ; zero B
    spmm_kernel<<<grid_sp, threads>>>(vals, rows, cols, (const float4*)B, A, n_edges);
    finish_kernel<<<grid_ew, threads>>>((float4*)acc, (const float4*)A, (float4*)B);

    // layer 3: B = Adj * A ; acc = (acc + B) / 4
    spmm_kernel<<<grid_sp, threads>>>(vals, rows, cols, (const float4*)A, B, n_edges);
    finish_last_kernel<<<grid_ew, threads>>>((float4*)acc, (const float4*)B);
}

// round 2
// speedup vs baseline: 1.6287x; 1.6287x over previous
#include <cuda_runtime.h>
#include <stdint.h>

#define USER_NUM 100000
#define ITEM_NUM 200000
#define NNODES   (USER_NUM + ITEM_NUM)   // 300000
#define EMB      64
#define TOT      (NNODES * EMB)
#define MAXE     2097152                 // >= 1,250,000 edges

#define SCAN_TPB 1024
#define NSCANBLK ((NNODES + SCAN_TPB - 1) / SCAN_TPB)   // 293

// ---- static scratch (no cudaMalloc allowed) ----
__device__ int   g_counts[NNODES];         // histogram, then reused as fill cursor
__device__ int   g_offsets[NNODES + 1];
__device__ int   g_blocksums[512];
__device__ int   g_csr_col[MAXE];
__device__ float g_csr_val[MAXE];
__device__ float g_bufA[TOT];              // e1 / e2 ping-pong
__device__ float g_bufB[TOT];

// ---------------------------------------------------------------------------
__global__ void zero_counts_kernel(int* __restrict__ counts) {
    int i = blockIdx.x * blockDim.x + threadIdx.x;
    if (i < NNODES) counts[i] = 0;
}

__global__ void hist_kernel(const int* __restrict__ rows, int* __restrict__ counts, int n) {
    int i = blockIdx.x * blockDim.x + threadIdx.x;
    if (i < n) atomicAdd(&counts[rows[i]], 1);
}

// block-local exclusive scan; emits block totals; zeroes counts (freeing it as cursor)
__global__ void scan1_kernel(int* __restrict__ counts, int* __restrict__ offsets,
                             int* __restrict__ blocksums) {
    __shared__ int sh[SCAN_TPB];
    int tid = threadIdx.x;
    int gid = blockIdx.x * SCAN_TPB + tid;
    int v = (gid < NNODES) ? counts[gid] : 0;
    sh[tid] = v;
    __syncthreads();
    for (int off = 1; off < SCAN_TPB; off <<= 1) {
        int t = (tid >= off) ? sh[tid - off] : 0;
        __syncthreads();
        sh[tid] += t;
        __syncthreads();
    }
    if (gid < NNODES) {
        offsets[gid] = sh[tid] - v;   // exclusive within block
        counts[gid]  = 0;             // becomes fill cursor
    }
    if (tid == SCAN_TPB - 1) blocksums[blockIdx.x] = sh[tid];
}

// single block: exclusive scan of block totals (NSCANBLK <= 512)
__global__ void scan2_kernel(int* __restrict__ blocksums, int nblk) {
    __shared__ int sh[512];
    int tid = threadIdx.x;
    int v = (tid < nblk) ? blocksums[tid] : 0;
    sh[tid] = v;
    __syncthreads();
    for (int off = 1; off < 512; off <<= 1) {
        int t = (tid >= off) ? sh[tid - off] : 0;
        __syncthreads();
        sh[tid] += t;
        __syncthreads();
    }
    if (tid < nblk) blocksums[tid] = sh[tid] - v;
}

__global__ void scan3_kernel(int* __restrict__ offsets, const int* __restrict__ blocksums,
                             int n_edges) {
    int gid = blockIdx.x * SCAN_TPB + threadIdx.x;
    if (gid < NNODES) offsets[gid] += blocksums[blockIdx.x];
    if (gid == 0) offsets[NNODES] = n_edges;
}

__global__ void fill_kernel(const int* __restrict__ rows, const int* __restrict__ cols,
                            const float* __restrict__ vals,
                            const int* __restrict__ offsets, int* __restrict__ cursor,
                            int* __restrict__ csr_col, float* __restrict__ csr_val, int n) {
    int e = blockIdx.x * blockDim.x + threadIdx.x;
    if (e >= n) return;
    int r = rows[e];
    int pos = offsets[r] + atomicAdd(&cursor[r], 1);
    csr_col[pos] = cols[e];
    csr_val[pos] = vals[e];
}

// ---------------------------------------------------------------------------
// CSR SpMM: 16 lanes per row, one float4 per lane. Fused epilogues:
//   MODE 0: next = s;  acc = ego(r) + s            (gather from ego = user||item)
//   MODE 1: next = s;  acc += s
//   MODE 2:            acc = (acc + s) * 0.25      (no next write)
// ---------------------------------------------------------------------------
template <int MODE>
__global__ void spmm_csr_kernel(const int* __restrict__ offsets,
                                const int* __restrict__ csr_col,
                                const float* __restrict__ csr_val,
                                const float4* __restrict__ x,      // MODE 1/2 gather src
                                const float4* __restrict__ user,
                                const float4* __restrict__ item,
                                float4* __restrict__ next,
                                float4* __restrict__ acc) {
    int t = blockIdx.x * blockDim.x + threadIdx.x;
    int r = t >> 4;
    int l = t & 15;
    if (r >= NNODES) return;

    int s = __ldg(offsets + r);
    int e = __ldg(offsets + r + 1);

    float4 a = make_float4(0.f, 0.f, 0.f, 0.f);
    for (int i = s; i < e; ++i) {
        int   c = __ldg(csr_col + i);
        float v = __ldg(csr_val + i);
        const float4* src;
        if (MODE == 0)
            src = (c < USER_NUM) ? (user + (long long)c * 16)
                                 : (item + (long long)(c - USER_NUM) * 16);
        else
            src = x + (long long)c * 16;
        float4 xv = __ldg(src + l);
        a.x += v * xv.x; a.y += v * xv.y; a.z += v * xv.z; a.w += v * xv.w;
    }

    long long idx = (long long)r * 16 + l;
    if (MODE == 0) {
        float4 ego = (r < USER_NUM) ? __ldg(&user[idx])
                                    : __ldg(&item[(long long)(r - USER_NUM) * 16 + l]);
        next[idx] = a;
        acc[idx]  = make_float4(ego.x + a.x, ego.y + a.y, ego.z + a.z, ego.w + a.w);
    } else if (MODE == 1) {
        next[idx] = a;
        float4 ac = acc[idx];
        acc[idx] = make_float4(ac.x + a.x, ac.y + a.y, ac.z + a.z, ac.w + a.w);
    } else {
        float4 ac = acc[idx];
        acc[idx] = make_float4((ac.x + a.x) * 0.25f, (ac.y + a.y) * 0.25f,
                               (ac.z + a.z) * 0.25f, (ac.w + a.w) * 0.25f);
    }
}

// ---------------------------------------------------------------------------
extern "C" void kernel_launch(void* const* d_in, const int* in_sizes, int n_in,
                              void* d_out, int out_size) {
    const float* user = (const float*)d_in[0];
    const float* item = (const float*)d_in[1];
    const float* vals = (const float*)d_in[2];
    const int*   rows = (const int*)  d_in[3];
    const int*   cols = (const int*)  d_in[4];
    const int n_edges = in_sizes[2];

    float* acc = (float*)d_out;

    int *counts, *offsets, *blocksums, *csr_col;
    float *csr_val, *A, *B;
    cudaGetSymbolAddress((void**)&counts,    g_counts);
    cudaGetSymbolAddress((void**)&offsets,   g_offsets);
    cudaGetSymbolAddress((void**)&blocksums, g_blocksums);
    cudaGetSymbolAddress((void**)&csr_col,   g_csr_col);
    cudaGetSymbolAddress((void**)&csr_val,   g_csr_val);
    cudaGetSymbolAddress((void**)&A,         g_bufA);
    cudaGetSymbolAddress((void**)&B,         g_bufB);

    const int TPB = 256;
    const int grid_nodes = (NNODES + TPB - 1) / TPB;
    const int grid_edges = (n_edges + TPB - 1) / TPB;
    const int grid_spmm  = (NNODES * 16 + TPB - 1) / TPB;

    // ---- CSR build (replayed in the graph; inputs are constant) ----
    zero_counts_kernel<<<grid_nodes, TPB>>>(counts);
    hist_kernel<<<grid_edges, TPB>>>(rows, counts, n_edges);
    scan1_kernel<<<NSCANBLK, SCAN_TPB>>>(counts, offsets, blocksums);
    scan2_kernel<<<1, 512>>>(blocksums, NSCANBLK);
    scan3_kernel<<<NSCANBLK, SCAN_TPB>>>(offsets, blocksums, n_edges);
    fill_kernel<<<grid_edges, TPB>>>(rows, cols, vals, offsets, counts,
                                     csr_col, csr_val, n_edges);

    // ---- 3 propagation layers, fully fused ----
    // layer 1: B = Adj*ego ; acc = ego + B
    spmm_csr_kernel<0><<<grid_spmm, TPB>>>(offsets, csr_col, csr_val, nullptr,
                                           (const float4*)user, (const float4*)item,
                                           (float4*)B, (float4*)acc);
    // layer 2: A = Adj*B ; acc += A
    spmm_csr_kernel<1><<<grid_spmm, TPB>>>(offsets, csr_col, csr_val, (const float4*)B,
                                           (const float4*)user, (const float4*)item,
                                           (float4*)A, (float4*)acc);
    // layer 3: acc = (acc + Adj*A) * 0.25
    spmm_csr_kernel<2><<<grid_spmm, TPB>>>(offsets, csr_col, csr_val, (const float4*)A,
                                           (const float4*)user, (const float4*)item,
                                           nullptr, (float4*)acc);
}